// round 2
// baseline (speedup 1.0000x reference)
#include <cuda_runtime.h>
#include <math.h>

#define IMH 384
#define IMW 384
#define TH 48
#define TW 48
#define PAD 24                 // out(y,x) uses im rows y-24+i, i in [0,48)
#define PIMH (IMH + 2*PAD)     // 432
#define PIMW (IMW + 2*PAD)     // 432
#define NB 16
#define NBIN2 (17*16)          // 272 (im bin 16 = out-of-bounds sentinel row)
#define MAXC (TH*TW)           // 2304

#define TPB 128
#define TILE_W 16
#define TILE_H 16

// ---- scratch (static device globals; no allocation allowed) ----
__device__ unsigned char g_imb[2 * PIMH * PIMW];  // padded binned image, 16 = OOB
__device__ unsigned char g_tb[2 * TH * TW];       // binned template
__device__ float         g_mm[8];                 // [im|t][b][min,max]
__device__ float         g_lut[MAXC + 1];         // c * ln(c), lut[0]=0

// ---------------- min/max reduction: 4 blocks (im b0, im b1, t b0, t b1) -----
__global__ void k_minmax(const float* __restrict__ im, const float* __restrict__ tp) {
    int which = blockIdx.x >> 1;   // 0 = im, 1 = template
    int b = blockIdx.x & 1;
    const float* src = which ? (tp + b * TH * TW) : (im + b * IMH * IMW);
    int n = which ? (TH * TW) : (IMH * IMW);

    float mn = 3.0e38f, mx = -3.0e38f;
    for (int i = threadIdx.x; i < n; i += blockDim.x) {
        float v = src[i];
        mn = fminf(mn, v);
        mx = fmaxf(mx, v);
    }
    __shared__ float smn[32], smx[32];
    for (int o = 16; o; o >>= 1) {
        mn = fminf(mn, __shfl_xor_sync(0xffffffffu, mn, o));
        mx = fmaxf(mx, __shfl_xor_sync(0xffffffffu, mx, o));
    }
    if ((threadIdx.x & 31) == 0) { smn[threadIdx.x >> 5] = mn; smx[threadIdx.x >> 5] = mx; }
    __syncthreads();
    if (threadIdx.x < 32) {
        int nw = blockDim.x >> 5;
        mn = (threadIdx.x < nw) ? smn[threadIdx.x] : 3.0e38f;
        mx = (threadIdx.x < nw) ? smx[threadIdx.x] : -3.0e38f;
        for (int o = 16; o; o >>= 1) {
            mn = fminf(mn, __shfl_xor_sync(0xffffffffu, mn, o));
            mx = fmaxf(mx, __shfl_xor_sync(0xffffffffu, mx, o));
        }
        if (threadIdx.x == 0) {
            g_mm[which * 4 + b * 2 + 0] = mn;
            g_mm[which * 4 + b * 2 + 1] = mx;
        }
    }
}

// ---------------- binning (matches jnp: floor(((v-mn)/(mx-mn)) * 15)) --------
__global__ void k_bin_im(const float* __restrict__ im) {
    int b = blockIdx.y;
    int idx = blockIdx.x * blockDim.x + threadIdx.x;
    if (idx >= PIMH * PIMW) return;
    int py = idx / PIMW, px = idx - py * PIMW;
    unsigned char q = 16;  // OOB sentinel
    if (py >= PAD && py < PAD + IMH && px >= PAD && px < PAD + IMW) {
        float mn = g_mm[b * 2 + 0], mx = g_mm[b * 2 + 1];
        float v = im[b * IMH * IMW + (py - PAD) * IMW + (px - PAD)];
        float r = (v - mn) / (mx - mn);
        q = (unsigned char)(int)floorf(r * 15.0f);
    }
    g_imb[b * PIMH * PIMW + idx] = q;
}

__global__ void k_bin_t(const float* __restrict__ tp) {
    int b = blockIdx.y;
    int idx = blockIdx.x * blockDim.x + threadIdx.x;
    if (idx >= TH * TW) return;
    float mn = g_mm[4 + b * 2 + 0], mx = g_mm[4 + b * 2 + 1];
    float v = tp[b * TH * TW + idx];
    float r = (v - mn) / (mx - mn);
    g_tb[b * TH * TW + idx] = (unsigned char)(int)floorf(r * 15.0f);
}

__global__ void k_lut() {
    int c = blockIdx.x * blockDim.x + threadIdx.x;
    if (c <= MAXC) g_lut[c] = (c > 0) ? (float)c * logf((float)c) : 0.0f;
}

// ---------------- main kernel ------------------------------------------------
// Dynamic smem layout (bytes):
//   [0)                 hist: u16 [272 bins][128 threads][2 pixels]  = 139264
//   [139264)            imtile: u8 [63 rows][64 stride]              = 4032
//   [143296)            ttile:  u8 [48*48]                           = 2304
//   [145600)            lut: f32 [2305]                              = 9220
#define SM_HIST   0
#define SM_IMT    139264
#define SM_TT     143296
#define SM_LUT    145600
#define SM_TOTAL  154824

__global__ void __launch_bounds__(TPB, 1) k_main(float* __restrict__ out) {
    extern __shared__ unsigned char smem[];
    unsigned short* hist  = (unsigned short*)(smem + SM_HIST);
    unsigned char*  imtile = smem + SM_IMT;
    unsigned char*  ttile  = smem + SM_TT;
    float*          lut    = (float*)(smem + SM_LUT);

    const int tid = threadIdx.x;
    const int b  = blockIdx.z;
    const int x0 = blockIdx.x * TILE_W;
    const int y0 = blockIdx.y * TILE_H;

    // zero histograms
    {
        unsigned* h4 = (unsigned*)(smem + SM_HIST);
        #pragma unroll 4
        for (int k = tid; k < (NBIN2 * TPB * 2 * 2) / 4; k += TPB) h4[k] = 0u;
    }
    for (int k = tid; k < TH * TW; k += TPB) ttile[k] = g_tb[b * TH * TW + k];
    for (int k = tid; k <= MAXC; k += TPB) lut[k] = g_lut[k];
    // window region of padded bin image: rows y0..y0+62, cols x0..x0+62
    for (int k = tid; k < 63 * 63; k += TPB) {
        int r = k / 63, c = k - r * 63;
        imtile[r * 64 + c] = g_imb[b * PIMH * PIMW + (y0 + r) * PIMW + (x0 + c)];
    }
    __syncthreads();

    const int cx = tid & 7;        // pixel-pair column (2 px each -> 16 wide)
    const int ry = tid >> 3;       // row 0..15
    const int hb = tid * 2;        // u16 index base within a bin slab
    const unsigned char* mbase = imtile + ry * 64 + 2 * cx;

    for (int i = 0; i < TH; i++) {
        const unsigned char* trow = ttile + i * TW;
        const unsigned char* mrow = mbase + i * 64;
        int tb = trow[0];
        int m0 = mrow[0];
        int m1 = mrow[1];
        #pragma unroll 4
        for (int j = 0; j < TW; j++) {
            int i0 = ((m0 << 4) + tb) * 256 + hb;
            int i1 = ((m1 << 4) + tb) * 256 + hb + 1;
            unsigned short h0 = hist[i0];
            unsigned short h1 = hist[i1];
            if (j + 1 < TW) {              // prefetch next (issues before the stores)
                tb = trow[j + 1];
                m0 = mrow[j + 1];
                m1 = mrow[j + 2];
            }
            hist[i0] = (unsigned short)(h0 + 1);
            hist[i1] = (unsigned short)(h1 + 1);
        }
    }
    __syncthreads();

    // ---- epilogue: KL from counts via MI identity ----
    const int oy = y0 + ry;
    const int ox = x0 + 2 * cx;
    #pragma unroll
    for (int p = 0; p < 2; p++) {
        const unsigned short* h = hist + hb + p;
        float Sxy = 0.0f, Sx = 0.0f;
        int N = 0;
        int cyAcc[16];
        #pragma unroll
        for (int by = 0; by < 16; by++) cyAcc[by] = 0;
        #pragma unroll
        for (int bx = 0; bx < 16; bx++) {   // note: bx==16 (OOB row) excluded
            int cxs = 0;
            #pragma unroll
            for (int by = 0; by < 16; by++) {
                int c = h[((bx << 4) + by) * 256];
                cxs += c;
                cyAcc[by] += c;
                Sxy += lut[c];
            }
            Sx += lut[cxs];
            N += cxs;
        }
        float Sy = 0.0f;
        #pragma unroll
        for (int by = 0; by < 16; by++) Sy += lut[cyAcc[by]];
        float kl = (Sxy - Sx - Sy + lut[N]) / (float)N;
        out[b * IMH * IMW + oy * IMW + ox + p] = kl;
    }
}

// ---------------- launch -----------------------------------------------------
extern "C" void kernel_launch(void* const* d_in, const int* in_sizes, int n_in,
                              void* d_out, int out_size) {
    const float* im = (const float*)d_in[0];
    const float* tp = (const float*)d_in[1];
    if (n_in >= 2 && in_sizes[0] < in_sizes[1]) {  // defensive: im is the big one
        const float* t = im; im = tp; tp = t;
    }
    float* out = (float*)d_out;

    cudaFuncSetAttribute(k_main, cudaFuncAttributeMaxDynamicSharedMemorySize, SM_TOTAL);

    k_minmax<<<4, 256>>>(im, tp);
    k_bin_im<<<dim3((PIMH * PIMW + 255) / 256, 2), 256>>>(im);
    k_bin_t<<<dim3((TH * TW + 255) / 256, 2), 256>>>(tp);
    k_lut<<<(MAXC + 256) / 256, 256>>>();
    k_main<<<dim3(IMW / TILE_W, IMH / TILE_H, 2), TPB, SM_TOTAL>>>(out);
}